// round 13
// baseline (speedup 1.0000x reference)
#include <cuda_runtime.h>
#include <cuda_fp16.h>

// Problem constants (fixed by the reference)
#define B_  8
#define N_  2048
#define L_  2048
#define Q_  512
#define D_  512
#define NH_ 4

// fp16 copy of the 4 embedding tables (4 * 512 * 512 * 2B = 2 MiB).
__device__ __align__(128) __half g_emb[NH_ * Q_ * D_];
// Scratch: per (b,h,l): w0,w1,w2 (float) + packed indices (int as float). 1 MiB.
__device__ __align__(128) float4 g_scr[B_ * NH_ * L_];

// ---------------------------------------------------------------------------
// Branch-free exact top-3 insert (stable: equal values keep the earlier index,
// matching jax.lax.top_k's lower-index-first tie break).
// ---------------------------------------------------------------------------
__device__ __forceinline__ void top3_insert(float v, int j,
                                            float& v0, float& v1, float& v2,
                                            int& i0, int& i1, int& i2) {
    bool g2 = v > v2;
    bool g1 = v > v1;
    bool g0 = v > v0;
    v2 = g1 ? v1 : (g2 ? v : v2);
    i2 = g1 ? i1 : (g2 ? j : i2);
    v1 = g0 ? v0 : (g1 ? v : v1);
    i1 = g0 ? i0 : (g1 ? j : i1);
    v0 = g0 ? v : v0;
    i0 = g0 ? j : i0;
}

// ---------------------------------------------------------------------------
// Kernel 1: fused [emb f32->fp16 convert prologue] + [top-3 + softmax].
// Grid = 512 blocks: (b, h, 128-l tile). 128 threads = 4 warps.
// Each thread owns 4 consecutive l's; warp j-loads are float4 -> 512B
// contiguous per op (4x fewer load issues than scalar). Warp w covers
// j in [w*128, w*128+128); 8-deep double-buffered pipeline.
// Prologue: 512 blocks x 128 thr x 16 elems = 1,048,576 = exactly the table.
// ---------------------------------------------------------------------------
__global__ __launch_bounds__(128)
void topk_kernel(const float* __restrict__ logits,
                 const float* __restrict__ e0,
                 const float* __restrict__ e1,
                 const float* __restrict__ e2,
                 const float* __restrict__ e3) {
    const int tid = threadIdx.x;

    // ---- convert prologue: 16 elems/thread ----
    {
        int base = blockIdx.x * 2048 + tid * 16;          // < 1,048,576
        int h = base >> 18;                               // 262144 elems/head
        int o = base & 262143;
        const float* src = (h == 0) ? e0 : (h == 1) ? e1 : (h == 2) ? e2 : e3;
        const float4* s = reinterpret_cast<const float4*>(src + o);
        float4 a = s[0], b4 = s[1], c4 = s[2], d4 = s[3];
        __half2 hh[8];
        hh[0] = __floats2half2_rn(a.x,  a.y);
        hh[1] = __floats2half2_rn(a.z,  a.w);
        hh[2] = __floats2half2_rn(b4.x, b4.y);
        hh[3] = __floats2half2_rn(b4.z, b4.w);
        hh[4] = __floats2half2_rn(c4.x, c4.y);
        hh[5] = __floats2half2_rn(c4.z, c4.w);
        hh[6] = __floats2half2_rn(d4.x, d4.y);
        hh[7] = __floats2half2_rn(d4.z, d4.w);
        uint4* dst = reinterpret_cast<uint4*>(g_emb + base);
        dst[0] = *reinterpret_cast<uint4*>(&hh[0]);
        dst[1] = *reinterpret_cast<uint4*>(&hh[4]);
    }

    // ---- top-3 over 4 l's per thread ----
    const int x  = blockIdx.x;           // 0 .. 511
    const int b  = x >> 6;
    const int h  = (x >> 4) & 3;
    const int lt = x & 15;
    const int l0 = lt * 128;

    const int wid  = tid >> 5;
    const int lane = tid & 31;
    const int jbase = wid * 128;

    // lane owns l = l0 + lane*4 .. +3
    const float* lp = logits + ((size_t)b * N_ + h * Q_ + jbase) * L_
                             + l0 + lane * 4;

    float v0[4], v1[4], v2[4];
    int   i0[4], i1[4], i2[4];
    #pragma unroll
    for (int k = 0; k < 4; ++k) {
        v0[k] = -1e30f; v1[k] = -1e30f; v2[k] = -1e30f;
        i0[k] = 0; i1[k] = 0; i2[k] = 0;
    }

    float4 buf[2][8];
    #pragma unroll
    for (int u = 0; u < 8; ++u)
        buf[0][u] = __ldg(reinterpret_cast<const float4*>(lp + (size_t)u * L_));

    #pragma unroll 2
    for (int c = 0; c < 16; ++c) {       // 16 chunks of 8 j = 128 j
        if (c < 15) {
            #pragma unroll
            for (int u = 0; u < 8; ++u)
                buf[(c + 1) & 1][u] = __ldg(reinterpret_cast<const float4*>(
                    lp + (size_t)((c + 1) * 8 + u) * L_));
        }
        const int jc = jbase + c * 8;
        #pragma unroll
        for (int u = 0; u < 8; ++u) {
            float4 v = buf[c & 1][u];
            int j = jc + u;
            top3_insert(v.x, j, v0[0], v1[0], v2[0], i0[0], i1[0], i2[0]);
            top3_insert(v.y, j, v0[1], v1[1], v2[1], i0[1], i1[1], i2[1]);
            top3_insert(v.z, j, v0[2], v1[2], v2[2], i0[2], i1[2], i2[2]);
            top3_insert(v.w, j, v0[3], v1[3], v2[3], i0[3], i1[3], i2[3]);
        }
    }

    __shared__ float sv[4][128][3];
    __shared__ short si[4][128][3];
    #pragma unroll
    for (int k = 0; k < 4; ++k) {
        const int l = lane * 4 + k;
        sv[wid][l][0] = v0[k]; sv[wid][l][1] = v1[k]; sv[wid][l][2] = v2[k];
        si[wid][l][0] = (short)i0[k]; si[wid][l][1] = (short)i1[k];
        si[wid][l][2] = (short)i2[k];
    }
    __syncthreads();

    // Merge the 4 j-ranges (ascending w keeps lower-j-first tie stability),
    // softmax, write scratch. One l per thread.
    {
        float m0 = -1e30f, m1 = -1e30f, m2 = -1e30f;
        int   j0 = 0, j1 = 0, j2 = 0;
        #pragma unroll
        for (int w = 0; w < 4; ++w) {
            #pragma unroll
            for (int r = 0; r < 3; ++r) {
                top3_insert(sv[w][tid][r], (int)si[w][tid][r],
                            m0, m1, m2, j0, j1, j2);
            }
        }
        float e1v = __expf(m1 - m0);
        float e2v = __expf(m2 - m0);
        float inv = 1.0f / (1.0f + e1v + e2v);
        int packed = j0 | (j1 << 10) | (j2 << 20);
        g_scr[((b * NH_ + h) << 11) + l0 + tid] =
            make_float4(inv, e1v * inv, e2v * inv, __int_as_float(packed));
    }
}

// ---------------------------------------------------------------------------
// Kernel 2: gather-combine.
// Block = (b, 32-l tile, 128-d chunk), 128 threads. Grid = 8*64*4 = 2048.
// Warp handles 8 l's in 4 l-PAIR passes: lane = (s = lane>>1, g = lane&1);
// lane loads uint4 (8 halves) at halves [s*8, s*8+8) of row(l_pair + g):
// both rows' 256B contiguous -> 4 wavefronts per op (full efficiency).
// Transpose buffer row stride 130 floats: STS.64 is 2-way (not 8-way),
// LDS 2-way, and the 32-wide l tile makes every STG a full 128B run.
// ---------------------------------------------------------------------------
__global__ __launch_bounds__(128)
void gather_kernel(float* __restrict__ out) {
    const int x  = blockIdx.x;           // 0 .. 2047
    const int b  = x >> 8;
    const int lt = (x >> 2) & 63;
    const int dc = x & 3;
    const int l0 = lt * 32;
    const int d0 = dc * 128;

    __shared__ float s_w[NH_ * 32 * 3];
    __shared__ int   s_off[NH_ * 32 * 3];
    __shared__ float s_t[32][130];       // transpose buffer (row = l)

    const int tid  = threadIdx.x;
    const int wid  = tid >> 5;
    const int lane = tid & 31;

    // Load scratch for 32 l's x 4 heads (128 float4, one per thread).
    {
        const int h = tid >> 5;          // 0..3
        const int l = tid & 31;
        float4 sc = g_scr[((b * NH_ + h) << 11) + l0 + l];
        int packed = __float_as_int(sc.w);
        int base = (h * 32 + l) * 3;
        s_w[base + 0] = sc.x;
        s_w[base + 1] = sc.y;
        s_w[base + 2] = sc.z;
        s_off[base + 0] = ((h << 9) + (packed         & 1023)) * D_ + d0;
        s_off[base + 1] = ((h << 9) + ((packed >> 10) & 1023)) * D_ + d0;
        s_off[base + 2] = ((h << 9) + ((packed >> 20) & 1023)) * D_ + d0;
    }
    __syncthreads();

    const int g = lane & 1;              // which row of the pair
    const int s = lane >> 1;             // 0..15: halves [s*8, s*8+8)

    #pragma unroll
    for (int p = 0; p < 4; ++p) {        // 4 l-pairs per warp
        const int l = wid * 8 + p * 2 + g;
        float acc[8];
        #pragma unroll
        for (int i = 0; i < 8; ++i) acc[i] = 0.0f;

        #pragma unroll
        for (int t = 0; t < 12; ++t) {
            const int h = t / 3, k = t - h * 3;
            const int base = (h * 32 + l) * 3 + k;
            const float w  = s_w[base];
            const int  off = s_off[base];
            uint4 r = *reinterpret_cast<const uint4*>(g_emb + off + s * 8);
            unsigned rr[4] = {r.x, r.y, r.z, r.w};
            #pragma unroll
            for (int q = 0; q < 4; ++q) {
                __half2 hv = *reinterpret_cast<__half2*>(&rr[q]);
                float2  f  = __half22float2(hv);
                acc[q * 2]     += w * f.x;
                acc[q * 2 + 1] += w * f.y;
            }
        }
        // s_t[l][s*8 + 2q .. +1] : STS.64, 2-way conflict with stride 130.
        float2* row = reinterpret_cast<float2*>(&s_t[l][s * 8]);
        row[0] = make_float2(acc[0], acc[1]);
        row[1] = make_float2(acc[2], acc[3]);
        row[2] = make_float2(acc[4], acc[5]);
        row[3] = make_float2(acc[6], acc[7]);
    }
    __syncthreads();

    // Store: out[b][d0+dd][l0+lane]; warp covers 32 consecutive l = 128B run.
    float* op = out + ((size_t)b * D_ + d0) * L_ + l0 + lane;
    #pragma unroll 8
    for (int i = 0; i < 32; ++i) {
        const int dd = wid * 32 + i;
        __stcs(op + (size_t)dd * L_, s_t[lane][dd]);
    }
}

// ---------------------------------------------------------------------------
extern "C" void kernel_launch(void* const* d_in, const int* in_sizes, int n_in,
                              void* d_out, int out_size) {
    (void)in_sizes; (void)n_in; (void)out_size;
    const float* logits = (const float*)d_in[0];
    const float* e0 = (const float*)d_in[1];
    const float* e1 = (const float*)d_in[2];
    const float* e2 = (const float*)d_in[3];
    const float* e3 = (const float*)d_in[4];
    float* out = (float*)d_out;

    topk_kernel<<<B_ * NH_ * (L_ / 128), 128>>>(logits, e0, e1, e2, e3);
    gather_kernel<<<B_ * (L_ / 32) * (D_ / 128), 128>>>(out);
}

// round 15
// speedup vs baseline: 1.2542x; 1.2542x over previous
#include <cuda_runtime.h>
#include <cuda_fp16.h>

// Problem constants (fixed by the reference)
#define B_  8
#define N_  2048
#define L_  2048
#define Q_  512
#define D_  512
#define NH_ 4
#define TL_  32   // l-tile for topk blocks
#define TLG_ 16   // l-tile for gather blocks

// fp16 copy of the 4 embedding tables (4 * 512 * 512 * 2B = 2 MiB).
__device__ __align__(128) __half g_emb[NH_ * Q_ * D_];
// Scratch: per (b,h,l): w0,w1,w2 (float) + packed indices (int as float). 1 MiB.
__device__ __align__(128) float4 g_scr[B_ * NH_ * L_];

// ---------------------------------------------------------------------------
// Branch-free exact top-3 insert (stable: equal values keep the earlier index,
// matching jax.lax.top_k's lower-index-first tie break).
// ---------------------------------------------------------------------------
__device__ __forceinline__ void top3_insert(float v, int j,
                                            float& v0, float& v1, float& v2,
                                            int& i0, int& i1, int& i2) {
    bool g2 = v > v2;
    bool g1 = v > v1;
    bool g0 = v > v0;
    v2 = g1 ? v1 : (g2 ? v : v2);
    i2 = g1 ? i1 : (g2 ? j : i2);
    v1 = g0 ? v0 : (g1 ? v : v1);
    i1 = g0 ? i0 : (g1 ? j : i1);
    v0 = g0 ? v : v0;
    i0 = g0 ? j : i0;
}

// ---------------------------------------------------------------------------
// Kernel 1: fused [emb f32->fp16 convert prologue] + [top-3 + softmax].
// (R12 structure, proven 30.4us.) Block = (b, h, 32-l tile), 128 threads.
// Prologue: 2048 blocks x 128 thr x 4 elems = 1,048,576 = exactly the table.
// Topk: warp w scans j in [w*128, w*128+128), lane = l. Double-buffered
// chunks of 16 with parity indexing (no register-copy loop).
// ---------------------------------------------------------------------------
__global__ __launch_bounds__(128)
void topk_kernel(const float* __restrict__ logits,
                 const float* __restrict__ e0,
                 const float* __restrict__ e1,
                 const float* __restrict__ e2,
                 const float* __restrict__ e3) {
    // ---- convert prologue ----
    {
        int base = blockIdx.x * 512 + threadIdx.x * 4;   // < 1,048,576
        int h = base >> 18;                               // 262144 elems/head
        int o = base & 262143;
        const float* src = (h == 0) ? e0 : (h == 1) ? e1 : (h == 2) ? e2 : e3;
        float4 a = *reinterpret_cast<const float4*>(src + o);
        __half2 h0 = __floats2half2_rn(a.x, a.y);
        __half2 h1 = __floats2half2_rn(a.z, a.w);
        uint2 packed;
        packed.x = *reinterpret_cast<unsigned*>(&h0);
        packed.y = *reinterpret_cast<unsigned*>(&h1);
        *reinterpret_cast<uint2*>(g_emb + base) = packed;
    }

    // ---- top-3, software-pipelined ----
    const int x  = blockIdx.x;           // 0 .. 2047
    const int b  = x >> 8;
    const int h  = (x >> 6) & 3;
    const int lt = x & 63;
    const int l0 = lt * TL_;

    const int wid  = threadIdx.x >> 5;
    const int lane = threadIdx.x & 31;

    const float* lp = logits + ((size_t)b * N_ + h * Q_ + wid * 128) * L_
                             + l0 + lane;

    float v0 = -1e30f, v1 = -1e30f, v2 = -1e30f;
    int   i0 = 0, i1 = 0, i2 = 0;
    const int jbase = wid * 128;

    float buf[2][16];
    #pragma unroll
    for (int u = 0; u < 16; ++u)
        buf[0][u] = __ldcs(lp + (size_t)u * L_);

    #pragma unroll
    for (int c = 0; c < 8; ++c) {        // 8 chunks of 16 = 128 elements
        if (c < 7) {
            #pragma unroll
            for (int u = 0; u < 16; ++u)
                buf[(c + 1) & 1][u] =
                    __ldcs(lp + (size_t)((c + 1) * 16 + u) * L_);
        }
        #pragma unroll
        for (int u = 0; u < 16; ++u)
            top3_insert(buf[c & 1][u], jbase + c * 16 + u,
                        v0, v1, v2, i0, i1, i2);
    }

    __shared__ float sv[4][TL_][3];
    __shared__ short si[4][TL_][3];
    sv[wid][lane][0] = v0; sv[wid][lane][1] = v1; sv[wid][lane][2] = v2;
    si[wid][lane][0] = (short)i0; si[wid][lane][1] = (short)i1;
    si[wid][lane][2] = (short)i2;
    __syncthreads();

    if (wid == 0) {
        float m0 = -1e30f, m1 = -1e30f, m2 = -1e30f;
        int   j0 = 0, j1 = 0, j2 = 0;
        #pragma unroll
        for (int s = 0; s < 4; ++s) {
            #pragma unroll
            for (int k = 0; k < 3; ++k) {
                top3_insert(sv[s][lane][k], (int)si[s][lane][k],
                            m0, m1, m2, j0, j1, j2);
            }
        }
        float e1v = __expf(m1 - m0);
        float e2v = __expf(m2 - m0);
        float inv = 1.0f / (1.0f + e1v + e2v);
        int packed = j0 | (j1 << 10) | (j2 << 20);
        g_scr[((b * NH_ + h) << 11) + l0 + lane] =
            make_float4(inv, e1v * inv, e2v * inv, __int_as_float(packed));
    }
}

// ---------------------------------------------------------------------------
// Kernel 2: gather-combine (R12 structure + conflict-free permuted transpose).
// Block = (b, 16-l tile, 256-d chunk), 128 threads. Grid = 8*128*2 = 2048.
// Loads: per (l, term) one warp-coalesced LDG.128 sweep (32 lanes x uint4 =
// 512B = the full 256-half row chunk); lane owns logical cols lane*8..+7.
//
// Transpose smem layout is PERMUTED: lane's q-th float2 (logical cols
// lane*8+2q, +1) is stored at phys col q*64 + lane*2. Each STS.64 thus
// writes 256 consecutive bytes -> conflict-free. Readback: thread
// (lc=tid&15, rb=tid>>4) reads phys col 8*i+rb of row lc; with row stride
// 258 floats the warp's bank pattern is 2*lc (+ rb parity) -> conflict-free.
// Logical dd for the store folds to 32*(i&7) + 2*(i>>3) + 8*(rb>>1) + (rb&1),
// a compile-time constant plus a per-thread precompute; bijective over 0..255.
// ---------------------------------------------------------------------------
__global__ __launch_bounds__(128)
void gather_kernel(float* __restrict__ out) {
    const int x  = blockIdx.x;           // 0 .. 2047
    const int b  = x >> 8;
    const int lt = (x >> 1) & 127;
    const int dc = x & 1;
    const int l0 = lt * TLG_;
    const int d0 = dc * 256;

    __shared__ float s_w[NH_ * TLG_ * 3];
    __shared__ int   s_off[NH_ * TLG_ * 3];
    __shared__ float s_t[TLG_][258];     // permuted transpose buffer (row = l)

    const int tid  = threadIdx.x;
    const int wid  = tid >> 5;
    const int lane = tid & 31;

    // Load scratch for the 16 l's x 4 heads (64 float4's, first 64 threads).
    if (tid < NH_ * TLG_) {
        const int h = tid >> 4;          // 0..3
        const int l = tid & 15;
        float4 sc = g_scr[((b * NH_ + h) << 11) + l0 + l];
        int packed = __float_as_int(sc.w);
        int base = (h * TLG_ + l) * 3;
        s_w[base + 0] = sc.x;
        s_w[base + 1] = sc.y;
        s_w[base + 2] = sc.z;
        s_off[base + 0] = ((h << 9) + (packed         & 1023)) * D_ + d0;
        s_off[base + 1] = ((h << 9) + ((packed >> 10) & 1023)) * D_ + d0;
        s_off[base + 2] = ((h << 9) + ((packed >> 20) & 1023)) * D_ + d0;
    }
    __syncthreads();

    // Each warp processes 4 l's; per l: 12 LDG.128 row-chunk loads (512B each).
    #pragma unroll 2
    for (int li = 0; li < 4; ++li) {
        const int l = wid * 4 + li;
        float acc[8];
        #pragma unroll
        for (int i = 0; i < 8; ++i) acc[i] = 0.0f;

        #pragma unroll
        for (int t = 0; t < 12; ++t) {
            const int h = t / 3, k = t - h * 3;
            const int base = (h * TLG_ + l) * 3 + k;
            const float w  = s_w[base];
            const int  off = s_off[base];
            uint4 r = *reinterpret_cast<const uint4*>(g_emb + off + lane * 8);
            unsigned rr[4] = {r.x, r.y, r.z, r.w};
            #pragma unroll
            for (int q = 0; q < 4; ++q) {
                __half2 hv = *reinterpret_cast<__half2*>(&rr[q]);
                float2  f  = __half22float2(hv);
                acc[q * 2]     += w * f.x;
                acc[q * 2 + 1] += w * f.y;
            }
        }
        // Permuted STS: q-th float2 -> phys float2-slot q*32 + lane
        // (= phys float col q*64 + lane*2). 256B-consecutive per STS.64 op.
        float2* row = reinterpret_cast<float2*>(&s_t[l][0]);
        #pragma unroll
        for (int q = 0; q < 4; ++q)
            row[q * 32 + lane] = make_float2(acc[q * 2], acc[q * 2 + 1]);
    }
    __syncthreads();

    // Store: thread (lc, rb) reads phys col 8*i+rb of row lc; logical
    // dd = 32*(i&7) + 2*(i>>3) + ddr, ddr = 8*(rb>>1) + (rb&1).
    const int lc = tid & 15;
    const int rb = tid >> 4;             // 0..7
    const int ddr = ((rb >> 1) << 3) + (rb & 1);
    float* op = out + ((size_t)b * D_ + d0 + ddr) * L_ + l0 + lc;
    #pragma unroll
    for (int i = 0; i < 32; ++i) {
        const int ddc = ((i & 7) << 5) + ((i >> 3) << 1);  // compile-time
        __stcs(op + (size_t)ddc * L_, s_t[lc][8 * i + rb]);
    }
}

// ---------------------------------------------------------------------------
extern "C" void kernel_launch(void* const* d_in, const int* in_sizes, int n_in,
                              void* d_out, int out_size) {
    (void)in_sizes; (void)n_in; (void)out_size;
    const float* logits = (const float*)d_in[0];
    const float* e0 = (const float*)d_in[1];
    const float* e1 = (const float*)d_in[2];
    const float* e2 = (const float*)d_in[3];
    const float* e3 = (const float*)d_in[4];
    float* out = (float*)d_out;

    topk_kernel<<<B_ * NH_ * (L_ / TL_), 128>>>(logits, e0, e1, e2, e3);
    gather_kernel<<<B_ * (L_ / TLG_) * (D_ / 256), 128>>>(out);
}

// round 16
// speedup vs baseline: 1.3351x; 1.0644x over previous
#include <cuda_runtime.h>
#include <cuda_fp16.h>

// Problem constants (fixed by the reference)
#define B_  8
#define N_  2048
#define L_  2048
#define Q_  512
#define D_  512
#define NH_ 4
#define TL_  32   // l-tile for topk blocks
#define TLG_ 16   // l-tile for gather blocks

#define NTOPK   (B_ * NH_ * (L_ / TL_))          // 2048 topk-role blocks
#define NGATHER (B_ * (L_ / TLG_) * (D_ / 256))  // 2048 gather-role blocks
#define NCONV   512                               // blocks doing emb convert
#define NFLAGS  (B_ * (L_ / TL_))                 // 512 per-(b,lt32) flags

// fp16 copy of the 4 embedding tables (2 MiB).
__device__ __align__(128) __half g_emb[NH_ * Q_ * D_];
// Scratch: per (b,h,l): w0,w1,w2 + packed indices. 1 MiB.
__device__ __align__(128) float4 g_scr[B_ * NH_ * L_];
// Handshake state (reset by zero_kernel each launch).
__device__ int g_flag[NFLAGS];
__device__ int g_conv;

// ---------------------------------------------------------------------------
__global__ void zero_kernel() {
    for (int i = threadIdx.x; i < NFLAGS; i += blockDim.x) g_flag[i] = 0;
    if (threadIdx.x == 0) g_conv = 0;
}

// ---------------------------------------------------------------------------
// Branch-free exact top-3 insert (stable: equal values keep the earlier index,
// matching jax.lax.top_k's lower-index-first tie break).
// ---------------------------------------------------------------------------
__device__ __forceinline__ void top3_insert(float v, int j,
                                            float& v0, float& v1, float& v2,
                                            int& i0, int& i1, int& i2) {
    bool g2 = v > v2;
    bool g1 = v > v1;
    bool g0 = v > v0;
    v2 = g1 ? v1 : (g2 ? v : v2);
    i2 = g1 ? i1 : (g2 ? j : i2);
    v1 = g0 ? v0 : (g1 ? v : v1);
    i1 = g0 ? i0 : (g1 ? j : i1);
    v0 = g0 ? v : v0;
    i0 = g0 ? j : i0;
}

// ---------------------------------------------------------------------------
// Fused kernel. Role by blockIdx.x:
//   [0, 2048)      : topk role  (R12-proven body; h-fastest tile order)
//   [2048, 4096)   : gather role (R15-proven body + flag/conv spin)
// Wave 1 is entirely topk blocks (never block -> guaranteed drain); gather
// blocks enter as topk blocks exit, overlapping topk tail with gather head.
// ---------------------------------------------------------------------------
__global__ __launch_bounds__(128)
void fused_kernel(const float* __restrict__ logits,
                  const float* __restrict__ e0,
                  const float* __restrict__ e1,
                  const float* __restrict__ e2,
                  const float* __restrict__ e3,
                  float* __restrict__ out) {
    const int bx = blockIdx.x;

    if (bx < NTOPK) {
        // ================= TOPK ROLE =================
        // ---- convert prologue (first 512 blocks; all wave-1 resident) ----
        if (bx < NCONV) {
            int base = bx * 2048 + threadIdx.x * 16;      // < 1,048,576
            int h = base >> 18;                           // 262144 elems/head
            int o = base & 262143;
            const float* src = (h == 0) ? e0 : (h == 1) ? e1
                             : (h == 2) ? e2 : e3;
            const float4* s = reinterpret_cast<const float4*>(src + o);
            float4 a = s[0], b4 = s[1], c4 = s[2], d4 = s[3];
            __half2 hh[8];
            hh[0] = __floats2half2_rn(a.x,  a.y);
            hh[1] = __floats2half2_rn(a.z,  a.w);
            hh[2] = __floats2half2_rn(b4.x, b4.y);
            hh[3] = __floats2half2_rn(b4.z, b4.w);
            hh[4] = __floats2half2_rn(c4.x, c4.y);
            hh[5] = __floats2half2_rn(c4.z, c4.w);
            hh[6] = __floats2half2_rn(d4.x, d4.y);
            hh[7] = __floats2half2_rn(d4.z, d4.w);
            uint4* dst = reinterpret_cast<uint4*>(g_emb + base);
            dst[0] = *reinterpret_cast<uint4*>(&hh[0]);
            dst[1] = *reinterpret_cast<uint4*>(&hh[4]);
            __threadfence();
            __syncthreads();
            if (threadIdx.x == 0) atomicAdd(&g_conv, 1);
        }

        // ---- top-3, software-pipelined (R12 body; h-fastest decode) ----
        const int b  = bx >> 8;
        const int lt = (bx >> 2) & 63;
        const int h  = bx & 3;
        const int l0 = lt * TL_;

        const int wid  = threadIdx.x >> 5;
        const int lane = threadIdx.x & 31;

        const float* lp = logits + ((size_t)b * N_ + h * Q_ + wid * 128) * L_
                                 + l0 + lane;

        float v0 = -1e30f, v1 = -1e30f, v2 = -1e30f;
        int   i0 = 0, i1 = 0, i2 = 0;
        const int jbase = wid * 128;

        float buf[2][16];
        #pragma unroll
        for (int u = 0; u < 16; ++u)
            buf[0][u] = __ldcs(lp + (size_t)u * L_);

        #pragma unroll
        for (int c = 0; c < 8; ++c) {    // 8 chunks of 16 = 128 elements
            if (c < 7) {
                #pragma unroll
                for (int u = 0; u < 16; ++u)
                    buf[(c + 1) & 1][u] =
                        __ldcs(lp + (size_t)((c + 1) * 16 + u) * L_);
            }
            #pragma unroll
            for (int u = 0; u < 16; ++u)
                top3_insert(buf[c & 1][u], jbase + c * 16 + u,
                            v0, v1, v2, i0, i1, i2);
        }

        __shared__ float sv[4][TL_][3];
        __shared__ short si[4][TL_][3];
        sv[wid][lane][0] = v0; sv[wid][lane][1] = v1; sv[wid][lane][2] = v2;
        si[wid][lane][0] = (short)i0; si[wid][lane][1] = (short)i1;
        si[wid][lane][2] = (short)i2;
        __syncthreads();

        if (wid == 0) {
            float m0 = -1e30f, m1 = -1e30f, m2 = -1e30f;
            int   j0 = 0, j1 = 0, j2 = 0;
            #pragma unroll
            for (int s = 0; s < 4; ++s) {
                #pragma unroll
                for (int k = 0; k < 3; ++k) {
                    top3_insert(sv[s][lane][k], (int)si[s][lane][k],
                                m0, m1, m2, j0, j1, j2);
                }
            }
            float e1v = __expf(m1 - m0);
            float e2v = __expf(m2 - m0);
            float inv = 1.0f / (1.0f + e1v + e2v);
            int packed = j0 | (j1 << 10) | (j2 << 20);
            g_scr[((b * NH_ + h) << 11) + l0 + lane] =
                make_float4(inv, e1v * inv, e2v * inv, __int_as_float(packed));
            // Release: all 32 scr stores -> fences -> syncwarp -> flag bump.
            __threadfence();
            __syncwarp();
            if (lane == 0) atomicAdd(&g_flag[(b << 6) + lt], 1);
        }
    } else {
        // ================= GATHER ROLE (R15 body + spin) =================
        const int x  = bx - NTOPK;       // 0 .. 2047
        const int b  = x >> 8;
        const int lt = (x >> 1) & 127;
        const int dc = x & 1;
        const int l0 = lt * TLG_;
        const int d0 = dc * 256;

        __shared__ float s_w[NH_ * TLG_ * 3];
        __shared__ int   s_off[NH_ * TLG_ * 3];
        __shared__ float s_t[TLG_][258]; // permuted transpose buffer

        const int tid  = threadIdx.x;
        const int wid  = tid >> 5;
        const int lane = tid & 31;

        // Wait for emb convert + this tile's 4 topk producers.
        if (tid == 0) {
            const int f = (b << 6) + (lt >> 1);
            while (*(volatile int*)&g_conv < NCONV) __nanosleep(128);
            while (*(volatile int*)&g_flag[f] < NH_) __nanosleep(128);
            __threadfence();             // acquire
        }
        __syncthreads();

        // Load scratch for the 16 l's x 4 heads.
        if (tid < NH_ * TLG_) {
            const int h = tid >> 4;
            const int l = tid & 15;
            float4 sc = g_scr[((b * NH_ + h) << 11) + l0 + l];
            int packed = __float_as_int(sc.w);
            int base = (h * TLG_ + l) * 3;
            s_w[base + 0] = sc.x;
            s_w[base + 1] = sc.y;
            s_w[base + 2] = sc.z;
            s_off[base + 0] = ((h << 9) + (packed         & 1023)) * D_ + d0;
            s_off[base + 1] = ((h << 9) + ((packed >> 10) & 1023)) * D_ + d0;
            s_off[base + 2] = ((h << 9) + ((packed >> 20) & 1023)) * D_ + d0;
        }
        __syncthreads();

        // Each warp: 4 l's; per l: 12 LDG.128 row-chunk loads (512B each).
        #pragma unroll 2
        for (int li = 0; li < 4; ++li) {
            const int l = wid * 4 + li;
            float acc[8];
            #pragma unroll
            for (int i = 0; i < 8; ++i) acc[i] = 0.0f;

            #pragma unroll
            for (int t = 0; t < 12; ++t) {
                const int h = t / 3, k = t - h * 3;
                const int base = (h * TLG_ + l) * 3 + k;
                const float w  = s_w[base];
                const int  off = s_off[base];
                uint4 r = *reinterpret_cast<const uint4*>(
                    g_emb + off + lane * 8);
                unsigned rr[4] = {r.x, r.y, r.z, r.w};
                #pragma unroll
                for (int q = 0; q < 4; ++q) {
                    __half2 hv = *reinterpret_cast<__half2*>(&rr[q]);
                    float2  f  = __half22float2(hv);
                    acc[q * 2]     += w * f.x;
                    acc[q * 2 + 1] += w * f.y;
                }
            }
            // Permuted STS: q-th float2 -> phys slot q*32 + lane (no conflicts)
            float2* row = reinterpret_cast<float2*>(&s_t[l][0]);
            #pragma unroll
            for (int q = 0; q < 4; ++q)
                row[q * 32 + lane] = make_float2(acc[q * 2], acc[q * 2 + 1]);
        }
        __syncthreads();

        // Readback + store (conflict-free; dd mapping bijective over 0..255).
        const int lc = tid & 15;
        const int rb = tid >> 4;         // 0..7
        const int ddr = ((rb >> 1) << 3) + (rb & 1);
        float* op = out + ((size_t)b * D_ + d0 + ddr) * L_ + l0 + lc;
        #pragma unroll
        for (int i = 0; i < 32; ++i) {
            const int ddc = ((i & 7) << 5) + ((i >> 3) << 1);
            __stcs(op + (size_t)ddc * L_, s_t[lc][8 * i + rb]);
        }
    }
}

// ---------------------------------------------------------------------------
extern "C" void kernel_launch(void* const* d_in, const int* in_sizes, int n_in,
                              void* d_out, int out_size) {
    (void)in_sizes; (void)n_in; (void)out_size;
    const float* logits = (const float*)d_in[0];
    const float* e0 = (const float*)d_in[1];
    const float* e1 = (const float*)d_in[2];
    const float* e2 = (const float*)d_in[3];
    const float* e3 = (const float*)d_in[4];
    float* out = (float*)d_out;

    zero_kernel<<<1, 128>>>();
    fused_kernel<<<NTOPK + NGATHER, 128>>>(logits, e0, e1, e2, e3, out);
}